// round 15
// baseline (speedup 1.0000x reference)
#include <cuda_runtime.h>
#include <cuda_fp16.h>
#include <cstdint>
#include <cstddef>

#define N_NODES 100000
#define N_EDGES 20000
#define F 128
#define NNZ_MAX 2000000
#define NSEG (N_EDGES + N_NODES)
#define SCAN_BLK 1024
#define NBLK ((NSEG + SCAN_BLK - 1) / SCAN_BLK)   // 118

// ---------------- scratch ----------------------------------------------------
__device__ __half g_node_msg[(size_t)N_NODES * F];
__device__ float  g_edge_agg[(size_t)N_EDGES * F];
__device__ __half g_he_msg[(size_t)N_EDGES * F];
__device__ int    g_cnt[NSEG];          // zero-init at load; self-reset each call
__device__ int    g_offsets[NSEG + 1];
__device__ int    g_cursors[NSEG];
__device__ int    g_entries[2 * NNZ_MAX];
__device__ int    g_scan_agg[NBLK];
__device__ int    g_scan_inc[NBLK];
__device__ int    g_scan_flag[NBLK];    // zero-init at load; reset by edgefill

__device__ __forceinline__ float sigmoidf(float x) {
    return 1.0f / (1.0f + __expf(-x));
}
__device__ __forceinline__ void mma_f16(float c[4],
    uint32_t a0, uint32_t a1, uint32_t a2, uint32_t a3,
    uint32_t b0, uint32_t b1)
{
    asm volatile(
        "mma.sync.aligned.m16n8k16.row.col.f32.f16.f16.f32 "
        "{%0,%1,%2,%3}, {%4,%5,%6,%7}, {%8,%9}, {%0,%1,%2,%3};"
        : "+f"(c[0]), "+f"(c[1]), "+f"(c[2]), "+f"(c[3])
        : "r"(a0), "r"(a1), "r"(a2), "r"(a3), "r"(b0), "r"(b1));
}

// ---------------- CSR build --------------------------------------------------
__global__ void hist_kernel(const int* __restrict__ node_idx,
                            const int* __restrict__ edge_idx,
                            int* __restrict__ cnt, int nnz) {
    int p = 4 * (blockIdx.x * blockDim.x + threadIdx.x);
    if (p + 4 <= nnz) {
        int4 e = *(const int4*)(edge_idx + p);
        int4 n = *(const int4*)(node_idx + p);
        atomicAdd(&cnt[e.x], 1);
        atomicAdd(&cnt[e.y], 1);
        atomicAdd(&cnt[e.z], 1);
        atomicAdd(&cnt[e.w], 1);
        atomicAdd(&cnt[N_EDGES + n.x], 1);
        atomicAdd(&cnt[N_EDGES + n.y], 1);
        atomicAdd(&cnt[N_EDGES + n.z], 1);
        atomicAdd(&cnt[N_EDGES + n.w], 1);
    } else {
        for (; p < nnz; p++) {
            atomicAdd(&cnt[__ldg(edge_idx + p)], 1);
            atomicAdd(&cnt[N_EDGES + __ldg(node_idx + p)], 1);
        }
    }
}

// single-pass exclusive scan with decoupled lookback; self-resets cnt.
__global__ void __launch_bounds__(SCAN_BLK) scan_onepass_kernel(
    int* __restrict__ cnt,
    int* __restrict__ offsets, int* __restrict__ cursors,
    int* __restrict__ agg, int* __restrict__ inc, int* __restrict__ flag,
    int n, int total)
{
    __shared__ int sh[SCAN_BLK];
    __shared__ int s_base;
    const int tid = threadIdx.x;
    const int bid = blockIdx.x;
    const int i = bid * SCAN_BLK + tid;

    int v = (i < n) ? cnt[i] : 0;
    sh[tid] = v;
    __syncthreads();
#pragma unroll
    for (int ofs = 1; ofs < SCAN_BLK; ofs <<= 1) {
        int add = (tid >= ofs) ? sh[tid - ofs] : 0;
        __syncthreads();
        sh[tid] += add;
        __syncthreads();
    }
    const int block_sum = sh[SCAN_BLK - 1];

    if (tid == 0) {
        if (bid == 0) {
            s_base = 0;
            inc[0] = block_sum;
            __threadfence();
            atomicExch(&flag[0], 2);
        } else {
            agg[bid] = block_sum;
            __threadfence();
            atomicExch(&flag[bid], 1);
            int excl = 0;
            int j = bid - 1;
            while (true) {
                int f;
                do { f = atomicAdd(&flag[j], 0); } while (f == 0);
                if (f == 2) {
                    excl += *(volatile int*)&inc[j];
                    break;
                }
                excl += *(volatile int*)&agg[j];
                j--;
            }
            s_base = excl;
            inc[bid] = excl + block_sum;
            __threadfence();
            atomicExch(&flag[bid], 2);
        }
    }
    __syncthreads();
    if (i < n) {
        int o = s_base + sh[tid] - v;
        offsets[i] = o;
        cursors[i] = o;
        cnt[i] = 0;                      // self-reset for next call
    }
    if (bid == 0 && tid == 0) offsets[n] = total;
}

// ---------------- GEMM body --------------------------------------------------
template <bool TWO>
__device__ __forceinline__ void gemm_body(
    __half (*Xs)[72], __half (*Ws)[72],
    const float* __restrict__ XA, const float* __restrict__ XB,
    const float* __restrict__ W, const float* __restrict__ bias,
    __half* __restrict__ out, int M, int m0)
{
    const int t    = threadIdx.x;
    const int lane = t & 31;
    const int wid  = t >> 5;
    const int wr   = wid >> 1;
    const int wc   = wid & 1;
    const int g    = lane >> 2;
    const int tig  = lane & 3;
    const int KTOT = TWO ? 256 : 128;

    float acc[2][8][4];
#pragma unroll
    for (int mt = 0; mt < 2; mt++)
#pragma unroll
        for (int nt = 0; nt < 8; nt++)
#pragma unroll
            for (int i = 0; i < 4; i++) acc[mt][nt][i] = 0.f;

    for (int kc = 0; kc < KTOT; kc += 64) {
        const float* Xsrc = (TWO && kc >= 128) ? XB : XA;
        const int koff    = (TWO && kc >= 128) ? kc - 128 : kc;

#pragma unroll
        for (int it = 0; it < 8; it++) {
            int i  = t + it * 256;
            int m  = i >> 4;
            int c4 = (i & 15) * 4;
            float4 v = make_float4(0.f, 0.f, 0.f, 0.f);
            if (m0 + m < M)
                v = *(const float4*)(Xsrc + (size_t)(m0 + m) * F + koff + c4);
            *(__half2*)&Xs[m][c4]     = __floats2half2_rn(v.x, v.y);
            *(__half2*)&Xs[m][c4 + 2] = __floats2half2_rn(v.z, v.w);
        }
#pragma unroll
        for (int it = 0; it < 8; it++) {
            int i  = t + it * 256;
            int n  = i >> 4;
            int c4 = (i & 15) * 4;
            float4 v = *(const float4*)(W + (size_t)n * KTOT + kc + c4);
            *(__half2*)&Ws[n][c4]     = __floats2half2_rn(v.x, v.y);
            *(__half2*)&Ws[n][c4 + 2] = __floats2half2_rn(v.z, v.w);
        }
        __syncthreads();

#pragma unroll
        for (int ks = 0; ks < 64; ks += 16) {
            uint32_t a[2][4];
#pragma unroll
            for (int mt = 0; mt < 2; mt++) {
                int mrow = wr * 32 + mt * 16 + g;
                a[mt][0] = *(const uint32_t*)&Xs[mrow][ks + 2 * tig];
                a[mt][1] = *(const uint32_t*)&Xs[mrow + 8][ks + 2 * tig];
                a[mt][2] = *(const uint32_t*)&Xs[mrow][ks + 2 * tig + 8];
                a[mt][3] = *(const uint32_t*)&Xs[mrow + 8][ks + 2 * tig + 8];
            }
#pragma unroll
            for (int nt = 0; nt < 8; nt++) {
                int nrow = wc * 64 + nt * 8 + g;
                uint32_t b0 = *(const uint32_t*)&Ws[nrow][ks + 2 * tig];
                uint32_t b1 = *(const uint32_t*)&Ws[nrow][ks + 2 * tig + 8];
                mma_f16(acc[0][nt], a[0][0], a[0][1], a[0][2], a[0][3], b0, b1);
                mma_f16(acc[1][nt], a[1][0], a[1][1], a[1][2], a[1][3], b0, b1);
            }
        }
        __syncthreads();
    }

#pragma unroll
    for (int mt = 0; mt < 2; mt++) {
        int r0 = m0 + wr * 32 + mt * 16 + g;
        int r1 = r0 + 8;
#pragma unroll
        for (int nt = 0; nt < 8; nt++) {
            int col = wc * 64 + nt * 8 + 2 * tig;
            float bb0 = __ldg(bias + col);
            float bb1 = __ldg(bias + col + 1);
            if (r0 < M) {
                __half2 h = __floats2half2_rn(sigmoidf(acc[mt][nt][0] + bb0),
                                              sigmoidf(acc[mt][nt][1] + bb1));
                *(__half2*)(out + (size_t)r0 * F + col) = h;
            }
            if (r1 < M) {
                __half2 h = __floats2half2_rn(sigmoidf(acc[mt][nt][2] + bb0),
                                              sigmoidf(acc[mt][nt][3] + bb1));
                *(__half2*)(out + (size_t)r1 * F + col) = h;
            }
        }
    }
}

// ---------------- segsum body: half-warp per row, 8 entries in flight --------
// 16 lanes x uint4 (16B) cover one 256B fp16 message row; each warp-wide
// LDG.128 gathers TWO entries. 4 load slots -> 8 entries in flight.
// fp32 accumulation (order change only). shfl.xor(16) merges the halves.
template <bool WRITE_AGG>
__device__ __forceinline__ void segsum_body(
    const __half* __restrict__ src,
    const int* __restrict__ entries,
    const int* __restrict__ offsets,
    const float* __restrict__ x,
    const float* __restrict__ gamma, const float* __restrict__ beta,
    const float* __restrict__ mean, const float* __restrict__ var,
    float* __restrict__ agg,
    float* __restrict__ out, int nseg, int seg_blk)
{
    int w = seg_blk * 8 + ((int)threadIdx.x >> 5);
    if (w >= nseg) return;
    const int lane = threadIdx.x & 31;
    const int sub  = lane >> 4;        // which entry of a pair
    const int fl   = lane & 15;        // which uint4 of the row
    int beg = __ldg(offsets + w);
    int end = __ldg(offsets + w + 1);

    float acc[8];
#pragma unroll
    for (int i = 0; i < 8; i++) acc[i] = 0.f;

    const uint4* s = (const uint4*)src;   // row stride = 16 uint4

#define ACC4(H) { \
        float2 f0 = __half22float2(*(__half2*)&(H).x); \
        float2 f1 = __half22float2(*(__half2*)&(H).y); \
        float2 f2 = __half22float2(*(__half2*)&(H).z); \
        float2 f3 = __half22float2(*(__half2*)&(H).w); \
        acc[0] += f0.x; acc[1] += f0.y; acc[2] += f1.x; acc[3] += f1.y; \
        acc[4] += f2.x; acc[5] += f2.y; acc[6] += f3.x; acc[7] += f3.y; }

    int j = beg;
    for (; j + 8 <= end; j += 8) {
        int e0 = __ldg(entries + j     + sub);
        int e1 = __ldg(entries + j + 2 + sub);
        int e2 = __ldg(entries + j + 4 + sub);
        int e3 = __ldg(entries + j + 6 + sub);
        uint4 h0 = __ldg(s + (size_t)e0 * 16 + fl);
        uint4 h1 = __ldg(s + (size_t)e1 * 16 + fl);
        uint4 h2 = __ldg(s + (size_t)e2 * 16 + fl);
        uint4 h3 = __ldg(s + (size_t)e3 * 16 + fl);
        ACC4(h0) ACC4(h1) ACC4(h2) ACC4(h3)
    }
    // predicated tail (<=7 entries), loads issued concurrently
    if (j < end) {
        uint4 z = make_uint4(0u, 0u, 0u, 0u);
        uint4 h0 = z, h1 = z, h2 = z, h3 = z;
        int i0 = j     + sub;
        int i1 = j + 2 + sub;
        int i2 = j + 4 + sub;
        int i3 = j + 6 + sub;
        if (i0 < end) { int e = __ldg(entries + i0); h0 = __ldg(s + (size_t)e * 16 + fl); }
        if (i1 < end) { int e = __ldg(entries + i1); h1 = __ldg(s + (size_t)e * 16 + fl); }
        if (i2 < end) { int e = __ldg(entries + i2); h2 = __ldg(s + (size_t)e * 16 + fl); }
        if (i3 < end) { int e = __ldg(entries + i3); h3 = __ldg(s + (size_t)e * 16 + fl); }
        ACC4(h0) ACC4(h1) ACC4(h2) ACC4(h3)
    }
#undef ACC4

    // merge the two half-warps (entry pairs)
#pragma unroll
    for (int i = 0; i < 8; i++)
        acc[i] += __shfl_xor_sync(0xffffffffu, acc[i], 16);

    if (sub == 0) {
        float4 r0 = make_float4(acc[0], acc[1], acc[2], acc[3]);
        float4 r1 = make_float4(acc[4], acc[5], acc[6], acc[7]);
        size_t base = (size_t)w * 32 + fl * 2;   // float4 units

        if (WRITE_AGG) {
            ((float4*)agg)[base]     = r0;
            ((float4*)agg)[base + 1] = r1;
        }

        float4 xv0 = __ldg((const float4*)x + base);
        float4 xv1 = __ldg((const float4*)x + base + 1);
        float4 ga0 = __ldg((const float4*)gamma + fl * 2);
        float4 ga1 = __ldg((const float4*)gamma + fl * 2 + 1);
        float4 be0 = __ldg((const float4*)beta + fl * 2);
        float4 be1 = __ldg((const float4*)beta + fl * 2 + 1);
        float4 me0 = __ldg((const float4*)mean + fl * 2);
        float4 me1 = __ldg((const float4*)mean + fl * 2 + 1);
        float4 va0 = __ldg((const float4*)var + fl * 2);
        float4 va1 = __ldg((const float4*)var + fl * 2 + 1);

        float4 o0, o1;
        o0.x = sigmoidf((xv0.x - me0.x) * (ga0.x * rsqrtf(va0.x + 1e-5f)) + be0.x + r0.x);
        o0.y = sigmoidf((xv0.y - me0.y) * (ga0.y * rsqrtf(va0.y + 1e-5f)) + be0.y + r0.y);
        o0.z = sigmoidf((xv0.z - me0.z) * (ga0.z * rsqrtf(va0.z + 1e-5f)) + be0.z + r0.z);
        o0.w = sigmoidf((xv0.w - me0.w) * (ga0.w * rsqrtf(va0.w + 1e-5f)) + be0.w + r0.w);
        o1.x = sigmoidf((xv1.x - me1.x) * (ga1.x * rsqrtf(va1.x + 1e-5f)) + be1.x + r1.x);
        o1.y = sigmoidf((xv1.y - me1.y) * (ga1.y * rsqrtf(va1.y + 1e-5f)) + be1.y + r1.y);
        o1.z = sigmoidf((xv1.z - me1.z) * (ga1.z * rsqrtf(va1.z + 1e-5f)) + be1.z + r1.z);
        o1.w = sigmoidf((xv1.w - me1.w) * (ga1.w * rsqrtf(va1.w + 1e-5f)) + be1.w + r1.w);
        ((float4*)out)[base]     = o0;
        ((float4*)out)[base + 1] = o1;
    }
}

// ---------------- fused edge-fill + GEMM1 (interleaved 5:2) ------------------
__global__ void __launch_bounds__(256) edgefill_gemm1_kernel(
    const int* __restrict__ node_idx, const int* __restrict__ edge_idx,
    int* __restrict__ cursors, int* __restrict__ entries, int nnz,
    int fill_blocks, int gemm_blocks,
    const float* __restrict__ X, const float* __restrict__ W,
    const float* __restrict__ bias, __half* __restrict__ out, int M,
    int* __restrict__ scan_flags)
{
    __shared__ __half Xs[128][72];
    __shared__ __half Ws[128][72];

    if (blockIdx.x == 0 && threadIdx.x < NBLK)
        scan_flags[threadIdx.x] = 0;     // reset for next call

    const int grp = blockIdx.x / 7;
    const int rem = blockIdx.x % 7;

    if (rem < 5) {
        int fid = grp * 5 + rem;
        if (fid >= fill_blocks) return;
        int p = 4 * (fid * blockDim.x + threadIdx.x);
        if (p + 4 <= nnz) {
            int4 e = *(const int4*)(edge_idx + p);
            int4 n = *(const int4*)(node_idx + p);
            int s0 = atomicAdd(&cursors[e.x], 1);
            int s1 = atomicAdd(&cursors[e.y], 1);
            int s2 = atomicAdd(&cursors[e.z], 1);
            int s3 = atomicAdd(&cursors[e.w], 1);
            entries[s0] = n.x;
            entries[s1] = n.y;
            entries[s2] = n.z;
            entries[s3] = n.w;
        } else {
            for (; p < nnz; p++) {
                int n = __ldg(node_idx + p);
                int e = __ldg(edge_idx + p);
                int s = atomicAdd(&cursors[e], 1);
                entries[s] = n;
            }
        }
    } else {
        int gid = grp * 2 + (rem - 5);
        if (gid >= gemm_blocks) return;
        gemm_body<false>(Xs, Ws, X, nullptr, W, bias, out, M, gid * 128);
    }
}

// ---------------- fused segsum-edge + node-fill (interleaved 5:4) ------------
__global__ void __launch_bounds__(256) segsumE_nodefill_kernel(
    const __half* __restrict__ node_msg,
    const int* __restrict__ entries,
    const int* __restrict__ offsets,
    const float* __restrict__ x1,
    const float* __restrict__ gamma, const float* __restrict__ beta,
    const float* __restrict__ mean, const float* __restrict__ var,
    float* __restrict__ edge_agg, float* __restrict__ x1_out,
    int seg_blocks,
    const int* __restrict__ node_idx, const int* __restrict__ edge_idx,
    int* __restrict__ cursors, int nnz, int fill_blocks)
{
    const int grp = blockIdx.x / 9;
    const int rem = blockIdx.x % 9;

    if (rem < 5) {
        int sid = grp * 5 + rem;
        if (sid >= seg_blocks) return;
        segsum_body<true>(node_msg, entries, offsets, x1,
                          gamma, beta, mean, var,
                          edge_agg, x1_out, N_EDGES, sid);
    } else {
        int fid = grp * 4 + (rem - 5);
        if (fid >= fill_blocks) return;
        int p = 4 * (fid * 256 + (int)threadIdx.x);
        int* entries_mut = (int*)entries;
        if (p + 4 <= nnz) {
            int4 e = *(const int4*)(edge_idx + p);
            int4 n = *(const int4*)(node_idx + p);
            int t0 = atomicAdd(&cursors[N_EDGES + n.x], 1);
            int t1 = atomicAdd(&cursors[N_EDGES + n.y], 1);
            int t2 = atomicAdd(&cursors[N_EDGES + n.z], 1);
            int t3 = atomicAdd(&cursors[N_EDGES + n.w], 1);
            entries_mut[t0] = e.x;
            entries_mut[t1] = e.y;
            entries_mut[t2] = e.z;
            entries_mut[t3] = e.w;
        } else {
            for (; p < nnz; p++) {
                int n = __ldg(node_idx + p);
                int e = __ldg(edge_idx + p);
                int q = atomicAdd(&cursors[N_EDGES + n], 1);
                entries_mut[q] = e;
            }
        }
    }
}

// standalone GEMM (used for GEMM2)
template <bool TWO>
__global__ void __launch_bounds__(256) gemm_f16_sig_kernel(
    const float* __restrict__ XA, const float* __restrict__ XB,
    const float* __restrict__ W, const float* __restrict__ bias,
    __half* __restrict__ out, int M)
{
    __shared__ __half Xs[128][72];
    __shared__ __half Ws[128][72];
    gemm_body<TWO>(Xs, Ws, XA, XB, W, bias, out, M, blockIdx.x * 128);
}

// standalone segsum (node direction)
template <bool WRITE_AGG>
__global__ void __launch_bounds__(256) segsum_fin_kernel(
    const __half* __restrict__ src,
    const int* __restrict__ entries,
    const int* __restrict__ offsets,
    const float* __restrict__ x,
    const float* __restrict__ gamma, const float* __restrict__ beta,
    const float* __restrict__ mean, const float* __restrict__ var,
    float* __restrict__ agg,
    float* __restrict__ out, int nseg)
{
    segsum_body<WRITE_AGG>(src, entries, offsets, x, gamma, beta, mean, var,
                           agg, out, nseg, blockIdx.x);
}

// ---------------- launch -----------------------------------------------------
extern "C" void kernel_launch(void* const* d_in, const int* in_sizes, int n_in,
                              void* d_out, int out_size)
{
    const float* x0        = (const float*)d_in[0];
    const float* x1        = (const float*)d_in[1];
    const int*   node_idx  = (const int*)d_in[2];
    const int*   edge_idx  = (const int*)d_in[3];
    const float* W_nh      = (const float*)d_in[4];
    const float* b_nh      = (const float*)d_in[5];
    const float* W_en      = (const float*)d_in[6];
    const float* b_en      = (const float*)d_in[7];
    const float* bn0_gamma = (const float*)d_in[8];
    const float* bn0_beta  = (const float*)d_in[9];
    const float* bn0_mean  = (const float*)d_in[10];
    const float* bn0_var   = (const float*)d_in[11];
    const float* bn1_gamma = (const float*)d_in[12];
    const float* bn1_beta  = (const float*)d_in[13];
    const float* bn1_mean  = (const float*)d_in[14];
    const float* bn1_var   = (const float*)d_in[15];

    float* out = (float*)d_out;
    const int nnz = in_sizes[2];

    __half *node_msg, *he_msg;
    float *edge_agg;
    int *cnt, *offsets, *cursors, *entries, *sagg, *sinc, *sflag;
    cudaGetSymbolAddress((void**)&node_msg, g_node_msg);
    cudaGetSymbolAddress((void**)&edge_agg, g_edge_agg);
    cudaGetSymbolAddress((void**)&he_msg,   g_he_msg);
    cudaGetSymbolAddress((void**)&cnt,      g_cnt);
    cudaGetSymbolAddress((void**)&offsets,  g_offsets);
    cudaGetSymbolAddress((void**)&cursors,  g_cursors);
    cudaGetSymbolAddress((void**)&entries,  g_entries);
    cudaGetSymbolAddress((void**)&sagg,     g_scan_agg);
    cudaGetSymbolAddress((void**)&sinc,     g_scan_inc);
    cudaGetSymbolAddress((void**)&sflag,    g_scan_flag);

    const int pair_blocks  = (nnz + 1023) / 1024;            // 4 pairs/thread
    const int gemm1_blocks = (N_NODES + 127) / 128;

    // --- hist (cnt arrives zeroed: static init first call, scan resets it) ---
    hist_kernel<<<(nnz / 4 + 256) / 256 + 1, 256>>>(node_idx, edge_idx, cnt, nnz);

    // --- one-pass scan (consumes cnt, writes offsets/cursors, re-zeros cnt) ---
    scan_onepass_kernel<<<NBLK, SCAN_BLK>>>(cnt, offsets, cursors,
                                            sagg, sinc, sflag, NSEG, 2 * nnz);

    // --- fused: edge-direction fill + GEMM1, interleaved 5:2 (+flag reset) ---
    {
        const int ngroups = max((pair_blocks + 4) / 5, (gemm1_blocks + 1) / 2);
        edgefill_gemm1_kernel<<<ngroups * 7, 256>>>(
            node_idx, edge_idx, cursors, entries, nnz,
            pair_blocks, gemm1_blocks,
            x0, W_nh, b_nh, node_msg, N_NODES, sflag);
    }

    // --- fused: segsum-edge (agg + x1_out) + node-direction fill, 5:4 ---
    {
        const int seg_blocks = (N_EDGES * 32 + 255) / 256;   // 2500
        const int ngroups = max((seg_blocks + 4) / 5, (pair_blocks + 3) / 4);
        segsumE_nodefill_kernel<<<ngroups * 9, 256>>>(
            node_msg, entries, offsets, x1,
            bn1_gamma, bn1_beta, bn1_mean, bn1_var,
            edge_agg, out + (size_t)N_NODES * F, seg_blocks,
            node_idx, edge_idx, cursors, nnz, pair_blocks);
    }

    // --- hyperedge messages ---
    gemm_f16_sig_kernel<true><<<(N_EDGES + 127) / 128, 256>>>(
        x1, edge_agg, W_en, b_en, he_msg, N_EDGES);

    // --- node segments: fused x0_out epilogue ---
    segsum_fin_kernel<false><<<(N_NODES * 32 + 255) / 256, 256>>>(
        he_msg, entries, offsets + N_EDGES, x0,
        bn0_gamma, bn0_beta, bn0_mean, bn0_var,
        nullptr, out, N_NODES);
}

// round 16
// speedup vs baseline: 1.0651x; 1.0651x over previous
#include <cuda_runtime.h>
#include <cuda_fp16.h>
#include <cstdint>
#include <cstddef>

#define N_NODES 100000
#define N_EDGES 20000
#define F 128
#define NNZ_MAX 2000000
#define NSEG (N_EDGES + N_NODES)
#define SCAN_BLK 1024
#define NBLK ((NSEG + SCAN_BLK - 1) / SCAN_BLK)   // 118

// ---------------- scratch ----------------------------------------------------
__device__ __half g_node_msg[(size_t)N_NODES * F];
__device__ float  g_edge_agg[(size_t)N_EDGES * F];
__device__ __half g_he_msg[(size_t)N_EDGES * F];
__device__ int    g_cnt[NSEG];          // zero-init at load; self-reset each call
__device__ int    g_offsets[NSEG + 1];
__device__ int    g_cursors[NSEG];
__device__ int    g_entries[2 * NNZ_MAX];
__device__ int    g_scan_agg[NBLK];
__device__ int    g_scan_inc[NBLK];
__device__ int    g_scan_flag[NBLK];    // zero-init at load; reset by edgefill

__device__ __forceinline__ float sigmoidf(float x) {
    return 1.0f / (1.0f + __expf(-x));
}
__device__ __forceinline__ void mma_f16(float c[4],
    uint32_t a0, uint32_t a1, uint32_t a2, uint32_t a3,
    uint32_t b0, uint32_t b1)
{
    asm volatile(
        "mma.sync.aligned.m16n8k16.row.col.f32.f16.f16.f32 "
        "{%0,%1,%2,%3}, {%4,%5,%6,%7}, {%8,%9}, {%0,%1,%2,%3};"
        : "+f"(c[0]), "+f"(c[1]), "+f"(c[2]), "+f"(c[3])
        : "r"(a0), "r"(a1), "r"(a2), "r"(a3), "r"(b0), "r"(b1));
}

// ---------------- CSR build --------------------------------------------------
__global__ void hist_kernel(const int* __restrict__ node_idx,
                            const int* __restrict__ edge_idx,
                            int* __restrict__ cnt, int nnz) {
    int p = 4 * (blockIdx.x * blockDim.x + threadIdx.x);
    if (p + 4 <= nnz) {
        int4 e = *(const int4*)(edge_idx + p);
        int4 n = *(const int4*)(node_idx + p);
        atomicAdd(&cnt[e.x], 1);
        atomicAdd(&cnt[e.y], 1);
        atomicAdd(&cnt[e.z], 1);
        atomicAdd(&cnt[e.w], 1);
        atomicAdd(&cnt[N_EDGES + n.x], 1);
        atomicAdd(&cnt[N_EDGES + n.y], 1);
        atomicAdd(&cnt[N_EDGES + n.z], 1);
        atomicAdd(&cnt[N_EDGES + n.w], 1);
    } else {
        for (; p < nnz; p++) {
            atomicAdd(&cnt[__ldg(edge_idx + p)], 1);
            atomicAdd(&cnt[N_EDGES + __ldg(node_idx + p)], 1);
        }
    }
}

// single-pass exclusive scan with decoupled lookback; self-resets cnt.
__global__ void __launch_bounds__(SCAN_BLK) scan_onepass_kernel(
    int* __restrict__ cnt,
    int* __restrict__ offsets, int* __restrict__ cursors,
    int* __restrict__ agg, int* __restrict__ inc, int* __restrict__ flag,
    int n, int total)
{
    __shared__ int sh[SCAN_BLK];
    __shared__ int s_base;
    const int tid = threadIdx.x;
    const int bid = blockIdx.x;
    const int i = bid * SCAN_BLK + tid;

    int v = (i < n) ? cnt[i] : 0;
    sh[tid] = v;
    __syncthreads();
#pragma unroll
    for (int ofs = 1; ofs < SCAN_BLK; ofs <<= 1) {
        int add = (tid >= ofs) ? sh[tid - ofs] : 0;
        __syncthreads();
        sh[tid] += add;
        __syncthreads();
    }
    const int block_sum = sh[SCAN_BLK - 1];

    if (tid == 0) {
        if (bid == 0) {
            s_base = 0;
            inc[0] = block_sum;
            __threadfence();
            atomicExch(&flag[0], 2);
        } else {
            agg[bid] = block_sum;
            __threadfence();
            atomicExch(&flag[bid], 1);
            int excl = 0;
            int j = bid - 1;
            while (true) {
                int f;
                do { f = atomicAdd(&flag[j], 0); } while (f == 0);
                if (f == 2) {
                    excl += *(volatile int*)&inc[j];
                    break;
                }
                excl += *(volatile int*)&agg[j];
                j--;
            }
            s_base = excl;
            inc[bid] = excl + block_sum;
            __threadfence();
            atomicExch(&flag[bid], 2);
        }
    }
    __syncthreads();
    if (i < n) {
        int o = s_base + sh[tid] - v;
        offsets[i] = o;
        cursors[i] = o;
        cnt[i] = 0;                      // self-reset for next call
    }
    if (bid == 0 && tid == 0) offsets[n] = total;
}

// ---------------- GEMM body --------------------------------------------------
template <bool TWO>
__device__ __forceinline__ void gemm_body(
    __half (*Xs)[72], __half (*Ws)[72],
    const float* __restrict__ XA, const float* __restrict__ XB,
    const float* __restrict__ W, const float* __restrict__ bias,
    __half* __restrict__ out, int M, int m0)
{
    const int t    = threadIdx.x;
    const int lane = t & 31;
    const int wid  = t >> 5;
    const int wr   = wid >> 1;
    const int wc   = wid & 1;
    const int g    = lane >> 2;
    const int tig  = lane & 3;
    const int KTOT = TWO ? 256 : 128;

    float acc[2][8][4];
#pragma unroll
    for (int mt = 0; mt < 2; mt++)
#pragma unroll
        for (int nt = 0; nt < 8; nt++)
#pragma unroll
            for (int i = 0; i < 4; i++) acc[mt][nt][i] = 0.f;

    for (int kc = 0; kc < KTOT; kc += 64) {
        const float* Xsrc = (TWO && kc >= 128) ? XB : XA;
        const int koff    = (TWO && kc >= 128) ? kc - 128 : kc;

#pragma unroll
        for (int it = 0; it < 8; it++) {
            int i  = t + it * 256;
            int m  = i >> 4;
            int c4 = (i & 15) * 4;
            float4 v = make_float4(0.f, 0.f, 0.f, 0.f);
            if (m0 + m < M)
                v = *(const float4*)(Xsrc + (size_t)(m0 + m) * F + koff + c4);
            *(__half2*)&Xs[m][c4]     = __floats2half2_rn(v.x, v.y);
            *(__half2*)&Xs[m][c4 + 2] = __floats2half2_rn(v.z, v.w);
        }
#pragma unroll
        for (int it = 0; it < 8; it++) {
            int i  = t + it * 256;
            int n  = i >> 4;
            int c4 = (i & 15) * 4;
            float4 v = *(const float4*)(W + (size_t)n * KTOT + kc + c4);
            *(__half2*)&Ws[n][c4]     = __floats2half2_rn(v.x, v.y);
            *(__half2*)&Ws[n][c4 + 2] = __floats2half2_rn(v.z, v.w);
        }
        __syncthreads();

#pragma unroll
        for (int ks = 0; ks < 64; ks += 16) {
            uint32_t a[2][4];
#pragma unroll
            for (int mt = 0; mt < 2; mt++) {
                int mrow = wr * 32 + mt * 16 + g;
                a[mt][0] = *(const uint32_t*)&Xs[mrow][ks + 2 * tig];
                a[mt][1] = *(const uint32_t*)&Xs[mrow + 8][ks + 2 * tig];
                a[mt][2] = *(const uint32_t*)&Xs[mrow][ks + 2 * tig + 8];
                a[mt][3] = *(const uint32_t*)&Xs[mrow + 8][ks + 2 * tig + 8];
            }
#pragma unroll
            for (int nt = 0; nt < 8; nt++) {
                int nrow = wc * 64 + nt * 8 + g;
                uint32_t b0 = *(const uint32_t*)&Ws[nrow][ks + 2 * tig];
                uint32_t b1 = *(const uint32_t*)&Ws[nrow][ks + 2 * tig + 8];
                mma_f16(acc[0][nt], a[0][0], a[0][1], a[0][2], a[0][3], b0, b1);
                mma_f16(acc[1][nt], a[1][0], a[1][1], a[1][2], a[1][3], b0, b1);
            }
        }
        __syncthreads();
    }

#pragma unroll
    for (int mt = 0; mt < 2; mt++) {
        int r0 = m0 + wr * 32 + mt * 16 + g;
        int r1 = r0 + 8;
#pragma unroll
        for (int nt = 0; nt < 8; nt++) {
            int col = wc * 64 + nt * 8 + 2 * tig;
            float bb0 = __ldg(bias + col);
            float bb1 = __ldg(bias + col + 1);
            if (r0 < M) {
                __half2 h = __floats2half2_rn(sigmoidf(acc[mt][nt][0] + bb0),
                                              sigmoidf(acc[mt][nt][1] + bb1));
                *(__half2*)(out + (size_t)r0 * F + col) = h;
            }
            if (r1 < M) {
                __half2 h = __floats2half2_rn(sigmoidf(acc[mt][nt][2] + bb0),
                                              sigmoidf(acc[mt][nt][3] + bb1));
                *(__half2*)(out + (size_t)r1 * F + col) = h;
            }
        }
    }
}

// ---------------- segsum HALF-WARP body (edge direction: long segments) ------
// 16 lanes x uint4 cover one 256B row; warp gathers TWO entries per LDG.128.
template <bool WRITE_AGG>
__device__ __forceinline__ void segsum_half_body(
    const __half* __restrict__ src,
    const int* __restrict__ entries,
    const int* __restrict__ offsets,
    const float* __restrict__ x,
    const float* __restrict__ gamma, const float* __restrict__ beta,
    const float* __restrict__ mean, const float* __restrict__ var,
    float* __restrict__ agg,
    float* __restrict__ out, int nseg, int seg_blk)
{
    int w = seg_blk * 8 + ((int)threadIdx.x >> 5);
    if (w >= nseg) return;
    const int lane = threadIdx.x & 31;
    const int sub  = lane >> 4;
    const int fl   = lane & 15;
    int beg = __ldg(offsets + w);
    int end = __ldg(offsets + w + 1);

    float acc[8];
#pragma unroll
    for (int i = 0; i < 8; i++) acc[i] = 0.f;

    const uint4* s = (const uint4*)src;

#define ACC4(H) { \
        float2 f0 = __half22float2(*(__half2*)&(H).x); \
        float2 f1 = __half22float2(*(__half2*)&(H).y); \
        float2 f2 = __half22float2(*(__half2*)&(H).z); \
        float2 f3 = __half22float2(*(__half2*)&(H).w); \
        acc[0] += f0.x; acc[1] += f0.y; acc[2] += f1.x; acc[3] += f1.y; \
        acc[4] += f2.x; acc[5] += f2.y; acc[6] += f3.x; acc[7] += f3.y; }

    int j = beg;
    for (; j + 8 <= end; j += 8) {
        int e0 = __ldg(entries + j     + sub);
        int e1 = __ldg(entries + j + 2 + sub);
        int e2 = __ldg(entries + j + 4 + sub);
        int e3 = __ldg(entries + j + 6 + sub);
        uint4 h0 = __ldg(s + (size_t)e0 * 16 + fl);
        uint4 h1 = __ldg(s + (size_t)e1 * 16 + fl);
        uint4 h2 = __ldg(s + (size_t)e2 * 16 + fl);
        uint4 h3 = __ldg(s + (size_t)e3 * 16 + fl);
        ACC4(h0) ACC4(h1) ACC4(h2) ACC4(h3)
    }
    if (j < end) {
        uint4 z = make_uint4(0u, 0u, 0u, 0u);
        uint4 h0 = z, h1 = z, h2 = z, h3 = z;
        int i0 = j     + sub;
        int i1 = j + 2 + sub;
        int i2 = j + 4 + sub;
        int i3 = j + 6 + sub;
        if (i0 < end) { int e = __ldg(entries + i0); h0 = __ldg(s + (size_t)e * 16 + fl); }
        if (i1 < end) { int e = __ldg(entries + i1); h1 = __ldg(s + (size_t)e * 16 + fl); }
        if (i2 < end) { int e = __ldg(entries + i2); h2 = __ldg(s + (size_t)e * 16 + fl); }
        if (i3 < end) { int e = __ldg(entries + i3); h3 = __ldg(s + (size_t)e * 16 + fl); }
        ACC4(h0) ACC4(h1) ACC4(h2) ACC4(h3)
    }
#undef ACC4

#pragma unroll
    for (int i = 0; i < 8; i++)
        acc[i] += __shfl_xor_sync(0xffffffffu, acc[i], 16);

    if (sub == 0) {
        float4 r0 = make_float4(acc[0], acc[1], acc[2], acc[3]);
        float4 r1 = make_float4(acc[4], acc[5], acc[6], acc[7]);
        size_t base = (size_t)w * 32 + fl * 2;

        if (WRITE_AGG) {
            ((float4*)agg)[base]     = r0;
            ((float4*)agg)[base + 1] = r1;
        }

        float4 xv0 = __ldg((const float4*)x + base);
        float4 xv1 = __ldg((const float4*)x + base + 1);
        float4 ga0 = __ldg((const float4*)gamma + fl * 2);
        float4 ga1 = __ldg((const float4*)gamma + fl * 2 + 1);
        float4 be0 = __ldg((const float4*)beta + fl * 2);
        float4 be1 = __ldg((const float4*)beta + fl * 2 + 1);
        float4 me0 = __ldg((const float4*)mean + fl * 2);
        float4 me1 = __ldg((const float4*)mean + fl * 2 + 1);
        float4 va0 = __ldg((const float4*)var + fl * 2);
        float4 va1 = __ldg((const float4*)var + fl * 2 + 1);

        float4 o0, o1;
        o0.x = sigmoidf((xv0.x - me0.x) * (ga0.x * rsqrtf(va0.x + 1e-5f)) + be0.x + r0.x);
        o0.y = sigmoidf((xv0.y - me0.y) * (ga0.y * rsqrtf(va0.y + 1e-5f)) + be0.y + r0.y);
        o0.z = sigmoidf((xv0.z - me0.z) * (ga0.z * rsqrtf(va0.z + 1e-5f)) + be0.z + r0.z);
        o0.w = sigmoidf((xv0.w - me0.w) * (ga0.w * rsqrtf(va0.w + 1e-5f)) + be0.w + r0.w);
        o1.x = sigmoidf((xv1.x - me1.x) * (ga1.x * rsqrtf(va1.x + 1e-5f)) + be1.x + r1.x);
        o1.y = sigmoidf((xv1.y - me1.y) * (ga1.y * rsqrtf(va1.y + 1e-5f)) + be1.y + r1.y);
        o1.z = sigmoidf((xv1.z - me1.z) * (ga1.z * rsqrtf(va1.z + 1e-5f)) + be1.z + r1.z);
        o1.w = sigmoidf((xv1.w - me1.w) * (ga1.w * rsqrtf(va1.w + 1e-5f)) + be1.w + r1.w);
        ((float4*)out)[base]     = o0;
        ((float4*)out)[base + 1] = o1;
    }
}

// ---------------- segsum QUAD body (node direction: short segments) ----------
// R14 measured-good form: full warp per row, MLP=4, parallel <=3 tail, 32 regs.
template <bool WRITE_AGG>
__device__ __forceinline__ void segsum_quad_body(
    const __half* __restrict__ src,
    const int* __restrict__ entries,
    const int* __restrict__ offsets,
    const float* __restrict__ x,
    const float* __restrict__ gamma, const float* __restrict__ beta,
    const float* __restrict__ mean, const float* __restrict__ var,
    float* __restrict__ agg,
    float* __restrict__ out, int nseg, int seg_blk)
{
    int w = seg_blk * 8 + ((int)threadIdx.x >> 5);
    if (w >= nseg) return;
    int lane = threadIdx.x & 31;
    int beg = __ldg(offsets + w);
    int end = __ldg(offsets + w + 1);

    float4 a0 = make_float4(0.f, 0.f, 0.f, 0.f);
    float4 a1 = a0, a2 = a0, a3 = a0;

    const uint2* s = (const uint2*)src;
    int j = beg;
    for (; j + 4 <= end; j += 4) {
        int e0 = __ldg(entries + j);
        int e1 = __ldg(entries + j + 1);
        int e2 = __ldg(entries + j + 2);
        int e3 = __ldg(entries + j + 3);
        uint2 h0 = __ldg(s + (size_t)e0 * 32 + lane);
        uint2 h1 = __ldg(s + (size_t)e1 * 32 + lane);
        uint2 h2 = __ldg(s + (size_t)e2 * 32 + lane);
        uint2 h3 = __ldg(s + (size_t)e3 * 32 + lane);
        {
            float2 f0 = __half22float2(*(__half2*)&h0.x);
            float2 f1 = __half22float2(*(__half2*)&h0.y);
            a0.x += f0.x; a0.y += f0.y; a0.z += f1.x; a0.w += f1.y;
        }
        {
            float2 f0 = __half22float2(*(__half2*)&h1.x);
            float2 f1 = __half22float2(*(__half2*)&h1.y);
            a1.x += f0.x; a1.y += f0.y; a1.z += f1.x; a1.w += f1.y;
        }
        {
            float2 f0 = __half22float2(*(__half2*)&h2.x);
            float2 f1 = __half22float2(*(__half2*)&h2.y);
            a2.x += f0.x; a2.y += f0.y; a2.z += f1.x; a2.w += f1.y;
        }
        {
            float2 f0 = __half22float2(*(__half2*)&h3.x);
            float2 f1 = __half22float2(*(__half2*)&h3.y);
            a3.x += f0.x; a3.y += f0.y; a3.z += f1.x; a3.w += f1.y;
        }
    }
    if (j < end) {
        uint2 h0 = make_uint2(0u, 0u), h1 = h0, h2 = h0;
        int e0 = __ldg(entries + j);
        h0 = __ldg(s + (size_t)e0 * 32 + lane);
        if (j + 1 < end) {
            int e1 = __ldg(entries + j + 1);
            h1 = __ldg(s + (size_t)e1 * 32 + lane);
        }
        if (j + 2 < end) {
            int e2 = __ldg(entries + j + 2);
            h2 = __ldg(s + (size_t)e2 * 32 + lane);
        }
        {
            float2 f0 = __half22float2(*(__half2*)&h0.x);
            float2 f1 = __half22float2(*(__half2*)&h0.y);
            a0.x += f0.x; a0.y += f0.y; a0.z += f1.x; a0.w += f1.y;
        }
        {
            float2 f0 = __half22float2(*(__half2*)&h1.x);
            float2 f1 = __half22float2(*(__half2*)&h1.y);
            a1.x += f0.x; a1.y += f0.y; a1.z += f1.x; a1.w += f1.y;
        }
        {
            float2 f0 = __half22float2(*(__half2*)&h2.x);
            float2 f1 = __half22float2(*(__half2*)&h2.y);
            a2.x += f0.x; a2.y += f0.y; a2.z += f1.x; a2.w += f1.y;
        }
    }
    float4 r;
    r.x = (a0.x + a1.x) + (a2.x + a3.x);
    r.y = (a0.y + a1.y) + (a2.y + a3.y);
    r.z = (a0.z + a1.z) + (a2.z + a3.z);
    r.w = (a0.w + a1.w) + (a2.w + a3.w);

    if (WRITE_AGG)
        *((float4*)agg + (size_t)w * 32 + lane) = r;

    float4 xv = __ldg((const float4*)x + (size_t)w * 32 + lane);
    float4 ga = __ldg((const float4*)gamma + lane);
    float4 be = __ldg((const float4*)beta + lane);
    float4 me = __ldg((const float4*)mean + lane);
    float4 va = __ldg((const float4*)var + lane);
    float4 o;
    o.x = sigmoidf((xv.x - me.x) * (ga.x * rsqrtf(va.x + 1e-5f)) + be.x + r.x);
    o.y = sigmoidf((xv.y - me.y) * (ga.y * rsqrtf(va.y + 1e-5f)) + be.y + r.y);
    o.z = sigmoidf((xv.z - me.z) * (ga.z * rsqrtf(va.z + 1e-5f)) + be.z + r.z);
    o.w = sigmoidf((xv.w - me.w) * (ga.w * rsqrtf(va.w + 1e-5f)) + be.w + r.w);
    *((float4*)out + (size_t)w * 32 + lane) = o;
}

// ---------------- fused edge-fill + GEMM1 (interleaved 5:2) ------------------
__global__ void __launch_bounds__(256) edgefill_gemm1_kernel(
    const int* __restrict__ node_idx, const int* __restrict__ edge_idx,
    int* __restrict__ cursors, int* __restrict__ entries, int nnz,
    int fill_blocks, int gemm_blocks,
    const float* __restrict__ X, const float* __restrict__ W,
    const float* __restrict__ bias, __half* __restrict__ out, int M,
    int* __restrict__ scan_flags)
{
    __shared__ __half Xs[128][72];
    __shared__ __half Ws[128][72];

    if (blockIdx.x == 0 && threadIdx.x < NBLK)
        scan_flags[threadIdx.x] = 0;     // reset for next call

    const int grp = blockIdx.x / 7;
    const int rem = blockIdx.x % 7;

    if (rem < 5) {
        int fid = grp * 5 + rem;
        if (fid >= fill_blocks) return;
        int p = 4 * (fid * blockDim.x + threadIdx.x);
        if (p + 4 <= nnz) {
            int4 e = *(const int4*)(edge_idx + p);
            int4 n = *(const int4*)(node_idx + p);
            int s0 = atomicAdd(&cursors[e.x], 1);
            int s1 = atomicAdd(&cursors[e.y], 1);
            int s2 = atomicAdd(&cursors[e.z], 1);
            int s3 = atomicAdd(&cursors[e.w], 1);
            entries[s0] = n.x;
            entries[s1] = n.y;
            entries[s2] = n.z;
            entries[s3] = n.w;
        } else {
            for (; p < nnz; p++) {
                int n = __ldg(node_idx + p);
                int e = __ldg(edge_idx + p);
                int s = atomicAdd(&cursors[e], 1);
                entries[s] = n;
            }
        }
    } else {
        int gid = grp * 2 + (rem - 5);
        if (gid >= gemm_blocks) return;
        gemm_body<false>(Xs, Ws, X, nullptr, W, bias, out, M, gid * 128);
    }
}

// ---------------- fused segsum-edge (half-warp) + node-fill (5:4) ------------
__global__ void __launch_bounds__(256) segsumE_nodefill_kernel(
    const __half* __restrict__ node_msg,
    const int* __restrict__ entries,
    const int* __restrict__ offsets,
    const float* __restrict__ x1,
    const float* __restrict__ gamma, const float* __restrict__ beta,
    const float* __restrict__ mean, const float* __restrict__ var,
    float* __restrict__ edge_agg, float* __restrict__ x1_out,
    int seg_blocks,
    const int* __restrict__ node_idx, const int* __restrict__ edge_idx,
    int* __restrict__ cursors, int nnz, int fill_blocks)
{
    const int grp = blockIdx.x / 9;
    const int rem = blockIdx.x % 9;

    if (rem < 5) {
        int sid = grp * 5 + rem;
        if (sid >= seg_blocks) return;
        segsum_half_body<true>(node_msg, entries, offsets, x1,
                               gamma, beta, mean, var,
                               edge_agg, x1_out, N_EDGES, sid);
    } else {
        int fid = grp * 4 + (rem - 5);
        if (fid >= fill_blocks) return;
        int p = 4 * (fid * 256 + (int)threadIdx.x);
        int* entries_mut = (int*)entries;
        if (p + 4 <= nnz) {
            int4 e = *(const int4*)(edge_idx + p);
            int4 n = *(const int4*)(node_idx + p);
            int t0 = atomicAdd(&cursors[N_EDGES + n.x], 1);
            int t1 = atomicAdd(&cursors[N_EDGES + n.y], 1);
            int t2 = atomicAdd(&cursors[N_EDGES + n.z], 1);
            int t3 = atomicAdd(&cursors[N_EDGES + n.w], 1);
            entries_mut[t0] = e.x;
            entries_mut[t1] = e.y;
            entries_mut[t2] = e.z;
            entries_mut[t3] = e.w;
        } else {
            for (; p < nnz; p++) {
                int n = __ldg(node_idx + p);
                int e = __ldg(edge_idx + p);
                int q = atomicAdd(&cursors[N_EDGES + n], 1);
                entries_mut[q] = e;
            }
        }
    }
}

// standalone GEMM (used for GEMM2)
template <bool TWO>
__global__ void __launch_bounds__(256) gemm_f16_sig_kernel(
    const float* __restrict__ XA, const float* __restrict__ XB,
    const float* __restrict__ W, const float* __restrict__ bias,
    __half* __restrict__ out, int M)
{
    __shared__ __half Xs[128][72];
    __shared__ __half Ws[128][72];
    gemm_body<TWO>(Xs, Ws, XA, XB, W, bias, out, M, blockIdx.x * 128);
}

// standalone segsum (node direction: quad body)
template <bool WRITE_AGG>
__global__ void __launch_bounds__(256) segsum_fin_kernel(
    const __half* __restrict__ src,
    const int* __restrict__ entries,
    const int* __restrict__ offsets,
    const float* __restrict__ x,
    const float* __restrict__ gamma, const float* __restrict__ beta,
    const float* __restrict__ mean, const float* __restrict__ var,
    float* __restrict__ agg,
    float* __restrict__ out, int nseg)
{
    segsum_quad_body<WRITE_AGG>(src, entries, offsets, x, gamma, beta,
                                mean, var, agg, out, nseg, blockIdx.x);
}

// ---------------- launch -----------------------------------------------------
extern "C" void kernel_launch(void* const* d_in, const int* in_sizes, int n_in,
                              void* d_out, int out_size)
{
    const float* x0        = (const float*)d_in[0];
    const float* x1        = (const float*)d_in[1];
    const int*   node_idx  = (const int*)d_in[2];
    const int*   edge_idx  = (const int*)d_in[3];
    const float* W_nh      = (const float*)d_in[4];
    const float* b_nh      = (const float*)d_in[5];
    const float* W_en      = (const float*)d_in[6];
    const float* b_en      = (const float*)d_in[7];
    const float* bn0_gamma = (const float*)d_in[8];
    const float* bn0_beta  = (const float*)d_in[9];
    const float* bn0_mean  = (const float*)d_in[10];
    const float* bn0_var   = (const float*)d_in[11];
    const float* bn1_gamma = (const float*)d_in[12];
    const float* bn1_beta  = (const float*)d_in[13];
    const float* bn1_mean  = (const float*)d_in[14];
    const float* bn1_var   = (const float*)d_in[15];

    float* out = (float*)d_out;
    const int nnz = in_sizes[2];

    __half *node_msg, *he_msg;
    float *edge_agg;
    int *cnt, *offsets, *cursors, *entries, *sagg, *sinc, *sflag;
    cudaGetSymbolAddress((void**)&node_msg, g_node_msg);
    cudaGetSymbolAddress((void**)&edge_agg, g_edge_agg);
    cudaGetSymbolAddress((void**)&he_msg,   g_he_msg);
    cudaGetSymbolAddress((void**)&cnt,      g_cnt);
    cudaGetSymbolAddress((void**)&offsets,  g_offsets);
    cudaGetSymbolAddress((void**)&cursors,  g_cursors);
    cudaGetSymbolAddress((void**)&entries,  g_entries);
    cudaGetSymbolAddress((void**)&sagg,     g_scan_agg);
    cudaGetSymbolAddress((void**)&sinc,     g_scan_inc);
    cudaGetSymbolAddress((void**)&sflag,    g_scan_flag);

    const int pair_blocks  = (nnz + 1023) / 1024;            // 4 pairs/thread
    const int gemm1_blocks = (N_NODES + 127) / 128;

    // --- hist (cnt arrives zeroed: static init first call, scan resets it) ---
    hist_kernel<<<(nnz / 4 + 256) / 256 + 1, 256>>>(node_idx, edge_idx, cnt, nnz);

    // --- one-pass scan (consumes cnt, writes offsets/cursors, re-zeros cnt) ---
    scan_onepass_kernel<<<NBLK, SCAN_BLK>>>(cnt, offsets, cursors,
                                            sagg, sinc, sflag, NSEG, 2 * nnz);

    // --- fused: edge-direction fill + GEMM1, interleaved 5:2 (+flag reset) ---
    {
        const int ngroups = max((pair_blocks + 4) / 5, (gemm1_blocks + 1) / 2);
        edgefill_gemm1_kernel<<<ngroups * 7, 256>>>(
            node_idx, edge_idx, cursors, entries, nnz,
            pair_blocks, gemm1_blocks,
            x0, W_nh, b_nh, node_msg, N_NODES, sflag);
    }

    // --- fused: segsum-edge (half-warp, agg + x1_out) + node-fill, 5:4 ---
    {
        const int seg_blocks = (N_EDGES * 32 + 255) / 256;   // 2500
        const int ngroups = max((seg_blocks + 4) / 5, (pair_blocks + 3) / 4);
        segsumE_nodefill_kernel<<<ngroups * 9, 256>>>(
            node_msg, entries, offsets, x1,
            bn1_gamma, bn1_beta, bn1_mean, bn1_var,
            edge_agg, out + (size_t)N_NODES * F, seg_blocks,
            node_idx, edge_idx, cursors, nnz, pair_blocks);
    }

    // --- hyperedge messages ---
    gemm_f16_sig_kernel<true><<<(N_EDGES + 127) / 128, 256>>>(
        x1, edge_agg, W_en, b_en, he_msg, N_EDGES);

    // --- node segments: quad body, fused x0_out epilogue ---
    segsum_fin_kernel<false><<<(N_NODES * 32 + 255) / 256, 256>>>(
        he_msg, entries, offsets + N_EDGES, x0,
        bn0_gamma, bn0_beta, bn0_mean, bn0_var,
        nullptr, out, N_NODES);
}

// round 17
// speedup vs baseline: 1.0805x; 1.0144x over previous
#include <cuda_runtime.h>
#include <cuda_fp16.h>
#include <cstdint>
#include <cstddef>

#define N_NODES 100000
#define N_EDGES 20000
#define F 128
#define NNZ_MAX 2000000
#define NSEG (N_EDGES + N_NODES)
#define SCAN_BLK 1024
#define NBLK ((NSEG + SCAN_BLK - 1) / SCAN_BLK)   // 118

// ---------------- scratch ----------------------------------------------------
__device__ __half g_node_msg[(size_t)N_NODES * F];
__device__ float  g_edge_agg[(size_t)N_EDGES * F];
__device__ __half g_he_msg[(size_t)N_EDGES * F];
__device__ int    g_cnt[NSEG];          // zero-init at load; self-reset each call
__device__ int    g_offsets[NSEG + 1];
__device__ int    g_cursors[NSEG];
__device__ int    g_entries[2 * NNZ_MAX];
__device__ int    g_scan_agg[NBLK];
__device__ int    g_scan_inc[NBLK];
__device__ int    g_scan_flag[NBLK];    // zero-init at load; reset by edgefill

__device__ __forceinline__ float sigmoidf(float x) {
    return 1.0f / (1.0f + __expf(-x));
}
__device__ __forceinline__ void mma_f16(float c[4],
    uint32_t a0, uint32_t a1, uint32_t a2, uint32_t a3,
    uint32_t b0, uint32_t b1)
{
    asm volatile(
        "mma.sync.aligned.m16n8k16.row.col.f32.f16.f16.f32 "
        "{%0,%1,%2,%3}, {%4,%5,%6,%7}, {%8,%9}, {%0,%1,%2,%3};"
        : "+f"(c[0]), "+f"(c[1]), "+f"(c[2]), "+f"(c[3])
        : "r"(a0), "r"(a1), "r"(a2), "r"(a3), "r"(b0), "r"(b1));
}

// ---------------- CSR build --------------------------------------------------
__global__ void hist_kernel(const int* __restrict__ node_idx,
                            const int* __restrict__ edge_idx,
                            int* __restrict__ cnt, int nnz) {
    int p = 4 * (blockIdx.x * blockDim.x + threadIdx.x);
    if (p + 4 <= nnz) {
        int4 e = *(const int4*)(edge_idx + p);
        int4 n = *(const int4*)(node_idx + p);
        atomicAdd(&cnt[e.x], 1);
        atomicAdd(&cnt[e.y], 1);
        atomicAdd(&cnt[e.z], 1);
        atomicAdd(&cnt[e.w], 1);
        atomicAdd(&cnt[N_EDGES + n.x], 1);
        atomicAdd(&cnt[N_EDGES + n.y], 1);
        atomicAdd(&cnt[N_EDGES + n.z], 1);
        atomicAdd(&cnt[N_EDGES + n.w], 1);
    } else {
        for (; p < nnz; p++) {
            atomicAdd(&cnt[__ldg(edge_idx + p)], 1);
            atomicAdd(&cnt[N_EDGES + __ldg(node_idx + p)], 1);
        }
    }
}

// single-pass exclusive scan with decoupled lookback; self-resets cnt.
__global__ void __launch_bounds__(SCAN_BLK) scan_onepass_kernel(
    int* __restrict__ cnt,
    int* __restrict__ offsets, int* __restrict__ cursors,
    int* __restrict__ agg, int* __restrict__ inc, int* __restrict__ flag,
    int n, int total)
{
    __shared__ int sh[SCAN_BLK];
    __shared__ int s_base;
    const int tid = threadIdx.x;
    const int bid = blockIdx.x;
    const int i = bid * SCAN_BLK + tid;

    int v = (i < n) ? cnt[i] : 0;
    sh[tid] = v;
    __syncthreads();
#pragma unroll
    for (int ofs = 1; ofs < SCAN_BLK; ofs <<= 1) {
        int add = (tid >= ofs) ? sh[tid - ofs] : 0;
        __syncthreads();
        sh[tid] += add;
        __syncthreads();
    }
    const int block_sum = sh[SCAN_BLK - 1];

    if (tid == 0) {
        if (bid == 0) {
            s_base = 0;
            inc[0] = block_sum;
            __threadfence();
            atomicExch(&flag[0], 2);
        } else {
            agg[bid] = block_sum;
            __threadfence();
            atomicExch(&flag[bid], 1);
            int excl = 0;
            int j = bid - 1;
            while (true) {
                int f;
                do { f = atomicAdd(&flag[j], 0); } while (f == 0);
                if (f == 2) {
                    excl += *(volatile int*)&inc[j];
                    break;
                }
                excl += *(volatile int*)&agg[j];
                j--;
            }
            s_base = excl;
            inc[bid] = excl + block_sum;
            __threadfence();
            atomicExch(&flag[bid], 2);
        }
    }
    __syncthreads();
    if (i < n) {
        int o = s_base + sh[tid] - v;
        offsets[i] = o;
        cursors[i] = o;
        cnt[i] = 0;                      // self-reset for next call
    }
    if (bid == 0 && tid == 0) offsets[n] = total;
}

// ---------------- GEMM body --------------------------------------------------
template <bool TWO>
__device__ __forceinline__ void gemm_body(
    __half (*Xs)[72], __half (*Ws)[72],
    const float* __restrict__ XA, const float* __restrict__ XB,
    const float* __restrict__ W, const float* __restrict__ bias,
    __half* __restrict__ out, int M, int m0)
{
    const int t    = threadIdx.x;
    const int lane = t & 31;
    const int wid  = t >> 5;
    const int wr   = wid >> 1;
    const int wc   = wid & 1;
    const int g    = lane >> 2;
    const int tig  = lane & 3;
    const int KTOT = TWO ? 256 : 128;

    float acc[2][8][4];
#pragma unroll
    for (int mt = 0; mt < 2; mt++)
#pragma unroll
        for (int nt = 0; nt < 8; nt++)
#pragma unroll
            for (int i = 0; i < 4; i++) acc[mt][nt][i] = 0.f;

    for (int kc = 0; kc < KTOT; kc += 64) {
        const float* Xsrc = (TWO && kc >= 128) ? XB : XA;
        const int koff    = (TWO && kc >= 128) ? kc - 128 : kc;

#pragma unroll
        for (int it = 0; it < 8; it++) {
            int i  = t + it * 256;
            int m  = i >> 4;
            int c4 = (i & 15) * 4;
            float4 v = make_float4(0.f, 0.f, 0.f, 0.f);
            if (m0 + m < M)
                v = *(const float4*)(Xsrc + (size_t)(m0 + m) * F + koff + c4);
            *(__half2*)&Xs[m][c4]     = __floats2half2_rn(v.x, v.y);
            *(__half2*)&Xs[m][c4 + 2] = __floats2half2_rn(v.z, v.w);
        }
#pragma unroll
        for (int it = 0; it < 8; it++) {
            int i  = t + it * 256;
            int n  = i >> 4;
            int c4 = (i & 15) * 4;
            float4 v = *(const float4*)(W + (size_t)n * KTOT + kc + c4);
            *(__half2*)&Ws[n][c4]     = __floats2half2_rn(v.x, v.y);
            *(__half2*)&Ws[n][c4 + 2] = __floats2half2_rn(v.z, v.w);
        }
        __syncthreads();

#pragma unroll
        for (int ks = 0; ks < 64; ks += 16) {
            uint32_t a[2][4];
#pragma unroll
            for (int mt = 0; mt < 2; mt++) {
                int mrow = wr * 32 + mt * 16 + g;
                a[mt][0] = *(const uint32_t*)&Xs[mrow][ks + 2 * tig];
                a[mt][1] = *(const uint32_t*)&Xs[mrow + 8][ks + 2 * tig];
                a[mt][2] = *(const uint32_t*)&Xs[mrow][ks + 2 * tig + 8];
                a[mt][3] = *(const uint32_t*)&Xs[mrow + 8][ks + 2 * tig + 8];
            }
#pragma unroll
            for (int nt = 0; nt < 8; nt++) {
                int nrow = wc * 64 + nt * 8 + g;
                uint32_t b0 = *(const uint32_t*)&Ws[nrow][ks + 2 * tig];
                uint32_t b1 = *(const uint32_t*)&Ws[nrow][ks + 2 * tig + 8];
                mma_f16(acc[0][nt], a[0][0], a[0][1], a[0][2], a[0][3], b0, b1);
                mma_f16(acc[1][nt], a[1][0], a[1][1], a[1][2], a[1][3], b0, b1);
            }
        }
        __syncthreads();
    }

#pragma unroll
    for (int mt = 0; mt < 2; mt++) {
        int r0 = m0 + wr * 32 + mt * 16 + g;
        int r1 = r0 + 8;
#pragma unroll
        for (int nt = 0; nt < 8; nt++) {
            int col = wc * 64 + nt * 8 + 2 * tig;
            float bb0 = __ldg(bias + col);
            float bb1 = __ldg(bias + col + 1);
            if (r0 < M) {
                __half2 h = __floats2half2_rn(sigmoidf(acc[mt][nt][0] + bb0),
                                              sigmoidf(acc[mt][nt][1] + bb1));
                *(__half2*)(out + (size_t)r0 * F + col) = h;
            }
            if (r1 < M) {
                __half2 h = __floats2half2_rn(sigmoidf(acc[mt][nt][2] + bb0),
                                              sigmoidf(acc[mt][nt][3] + bb1));
                *(__half2*)(out + (size_t)r1 * F + col) = h;
            }
        }
    }
}

#define ACC4(H) { \
        float2 f0 = __half22float2(*(__half2*)&(H).x); \
        float2 f1 = __half22float2(*(__half2*)&(H).y); \
        float2 f2 = __half22float2(*(__half2*)&(H).z); \
        float2 f3 = __half22float2(*(__half2*)&(H).w); \
        acc[0] += f0.x; acc[1] += f0.y; acc[2] += f1.x; acc[3] += f1.y; \
        acc[4] += f2.x; acc[5] += f2.y; acc[6] += f3.x; acc[7] += f3.y; }

// ---------------- segsum HALF-WARP-MERGE body (edge: long segments) ----------
// 16 lanes x uint4 cover one 256B row; warp gathers TWO entries per LDG.128;
// shfl.xor(16) merges. Measured-good in fused edge kernel.
template <bool WRITE_AGG>
__device__ __forceinline__ void segsum_half_body(
    const __half* __restrict__ src,
    const int* __restrict__ entries,
    const int* __restrict__ offsets,
    const float* __restrict__ x,
    const float* __restrict__ gamma, const float* __restrict__ beta,
    const float* __restrict__ mean, const float* __restrict__ var,
    float* __restrict__ agg,
    float* __restrict__ out, int nseg, int seg_blk)
{
    int w = seg_blk * 8 + ((int)threadIdx.x >> 5);
    if (w >= nseg) return;
    const int lane = threadIdx.x & 31;
    const int sub  = lane >> 4;
    const int fl   = lane & 15;
    int beg = __ldg(offsets + w);
    int end = __ldg(offsets + w + 1);

    float acc[8];
#pragma unroll
    for (int i = 0; i < 8; i++) acc[i] = 0.f;

    const uint4* s = (const uint4*)src;

    int j = beg;
    for (; j + 8 <= end; j += 8) {
        int e0 = __ldg(entries + j     + sub);
        int e1 = __ldg(entries + j + 2 + sub);
        int e2 = __ldg(entries + j + 4 + sub);
        int e3 = __ldg(entries + j + 6 + sub);
        uint4 h0 = __ldg(s + (size_t)e0 * 16 + fl);
        uint4 h1 = __ldg(s + (size_t)e1 * 16 + fl);
        uint4 h2 = __ldg(s + (size_t)e2 * 16 + fl);
        uint4 h3 = __ldg(s + (size_t)e3 * 16 + fl);
        ACC4(h0) ACC4(h1) ACC4(h2) ACC4(h3)
    }
    if (j < end) {
        uint4 z = make_uint4(0u, 0u, 0u, 0u);
        uint4 h0 = z, h1 = z, h2 = z, h3 = z;
        int i0 = j     + sub;
        int i1 = j + 2 + sub;
        int i2 = j + 4 + sub;
        int i3 = j + 6 + sub;
        if (i0 < end) { int e = __ldg(entries + i0); h0 = __ldg(s + (size_t)e * 16 + fl); }
        if (i1 < end) { int e = __ldg(entries + i1); h1 = __ldg(s + (size_t)e * 16 + fl); }
        if (i2 < end) { int e = __ldg(entries + i2); h2 = __ldg(s + (size_t)e * 16 + fl); }
        if (i3 < end) { int e = __ldg(entries + i3); h3 = __ldg(s + (size_t)e * 16 + fl); }
        ACC4(h0) ACC4(h1) ACC4(h2) ACC4(h3)
    }

#pragma unroll
    for (int i = 0; i < 8; i++)
        acc[i] += __shfl_xor_sync(0xffffffffu, acc[i], 16);

    if (sub == 0) {
        float4 r0 = make_float4(acc[0], acc[1], acc[2], acc[3]);
        float4 r1 = make_float4(acc[4], acc[5], acc[6], acc[7]);
        size_t base = (size_t)w * 32 + fl * 2;

        if (WRITE_AGG) {
            ((float4*)agg)[base]     = r0;
            ((float4*)agg)[base + 1] = r1;
        }

        float4 xv0 = __ldg((const float4*)x + base);
        float4 xv1 = __ldg((const float4*)x + base + 1);
        float4 ga0 = __ldg((const float4*)gamma + fl * 2);
        float4 ga1 = __ldg((const float4*)gamma + fl * 2 + 1);
        float4 be0 = __ldg((const float4*)beta + fl * 2);
        float4 be1 = __ldg((const float4*)beta + fl * 2 + 1);
        float4 me0 = __ldg((const float4*)mean + fl * 2);
        float4 me1 = __ldg((const float4*)mean + fl * 2 + 1);
        float4 va0 = __ldg((const float4*)var + fl * 2);
        float4 va1 = __ldg((const float4*)var + fl * 2 + 1);

        float4 o0, o1;
        o0.x = sigmoidf((xv0.x - me0.x) * (ga0.x * rsqrtf(va0.x + 1e-5f)) + be0.x + r0.x);
        o0.y = sigmoidf((xv0.y - me0.y) * (ga0.y * rsqrtf(va0.y + 1e-5f)) + be0.y + r0.y);
        o0.z = sigmoidf((xv0.z - me0.z) * (ga0.z * rsqrtf(va0.z + 1e-5f)) + be0.z + r0.z);
        o0.w = sigmoidf((xv0.w - me0.w) * (ga0.w * rsqrtf(va0.w + 1e-5f)) + be0.w + r0.w);
        o1.x = sigmoidf((xv1.x - me1.x) * (ga1.x * rsqrtf(va1.x + 1e-5f)) + be1.x + r1.x);
        o1.y = sigmoidf((xv1.y - me1.y) * (ga1.y * rsqrtf(va1.y + 1e-5f)) + be1.y + r1.y);
        o1.z = sigmoidf((xv1.z - me1.z) * (ga1.z * rsqrtf(va1.z + 1e-5f)) + be1.z + r1.z);
        o1.w = sigmoidf((xv1.w - me1.w) * (ga1.w * rsqrtf(va1.w + 1e-5f)) + be1.w + r1.w);
        ((float4*)out)[base]     = o0;
        ((float4*)out)[base + 1] = o1;
    }
}

// ---------------- segsum HALF-WARP-PER-SEGMENT body (node: short segments) ---
// Each 16-lane half-warp owns ONE segment; 16 lanes x uint4 = full 256B row
// per LDG.128; MLP=4 entries per half -> 8 gathers in flight per warp.
// No shuffle merge, ~34 regs, full occupancy.
__global__ void __launch_bounds__(256) segsum_node_kernel(
    const __half* __restrict__ src,
    const int* __restrict__ entries,
    const int* __restrict__ offsets,
    const float* __restrict__ x,
    const float* __restrict__ gamma, const float* __restrict__ beta,
    const float* __restrict__ mean, const float* __restrict__ var,
    float* __restrict__ out, int nseg)
{
    int w = blockIdx.x * 16 + ((int)threadIdx.x >> 4);
    if (w >= nseg) return;
    const int fl = threadIdx.x & 15;
    int beg = __ldg(offsets + w);
    int end = __ldg(offsets + w + 1);

    float acc[8];
#pragma unroll
    for (int i = 0; i < 8; i++) acc[i] = 0.f;

    const uint4* s = (const uint4*)src;

    int j = beg;
    for (; j + 4 <= end; j += 4) {
        int e0 = __ldg(entries + j);
        int e1 = __ldg(entries + j + 1);
        int e2 = __ldg(entries + j + 2);
        int e3 = __ldg(entries + j + 3);
        uint4 h0 = __ldg(s + (size_t)e0 * 16 + fl);
        uint4 h1 = __ldg(s + (size_t)e1 * 16 + fl);
        uint4 h2 = __ldg(s + (size_t)e2 * 16 + fl);
        uint4 h3 = __ldg(s + (size_t)e3 * 16 + fl);
        ACC4(h0) ACC4(h1) ACC4(h2) ACC4(h3)
    }
    if (j < end) {
        uint4 z = make_uint4(0u, 0u, 0u, 0u);
        uint4 h0 = z, h1 = z, h2 = z;
        int e0 = __ldg(entries + j);
        h0 = __ldg(s + (size_t)e0 * 16 + fl);
        if (j + 1 < end) {
            int e1 = __ldg(entries + j + 1);
            h1 = __ldg(s + (size_t)e1 * 16 + fl);
        }
        if (j + 2 < end) {
            int e2 = __ldg(entries + j + 2);
            h2 = __ldg(s + (size_t)e2 * 16 + fl);
        }
        ACC4(h0) ACC4(h1) ACC4(h2)
    }

    float4 r0 = make_float4(acc[0], acc[1], acc[2], acc[3]);
    float4 r1 = make_float4(acc[4], acc[5], acc[6], acc[7]);
    size_t base = (size_t)w * 32 + fl * 2;

    float4 xv0 = __ldg((const float4*)x + base);
    float4 xv1 = __ldg((const float4*)x + base + 1);
    float4 ga0 = __ldg((const float4*)gamma + fl * 2);
    float4 ga1 = __ldg((const float4*)gamma + fl * 2 + 1);
    float4 be0 = __ldg((const float4*)beta + fl * 2);
    float4 be1 = __ldg((const float4*)beta + fl * 2 + 1);
    float4 me0 = __ldg((const float4*)mean + fl * 2);
    float4 me1 = __ldg((const float4*)mean + fl * 2 + 1);
    float4 va0 = __ldg((const float4*)var + fl * 2);
    float4 va1 = __ldg((const float4*)var + fl * 2 + 1);

    float4 o0, o1;
    o0.x = sigmoidf((xv0.x - me0.x) * (ga0.x * rsqrtf(va0.x + 1e-5f)) + be0.x + r0.x);
    o0.y = sigmoidf((xv0.y - me0.y) * (ga0.y * rsqrtf(va0.y + 1e-5f)) + be0.y + r0.y);
    o0.z = sigmoidf((xv0.z - me0.z) * (ga0.z * rsqrtf(va0.z + 1e-5f)) + be0.z + r0.z);
    o0.w = sigmoidf((xv0.w - me0.w) * (ga0.w * rsqrtf(va0.w + 1e-5f)) + be0.w + r0.w);
    o1.x = sigmoidf((xv1.x - me1.x) * (ga1.x * rsqrtf(va1.x + 1e-5f)) + be1.x + r1.x);
    o1.y = sigmoidf((xv1.y - me1.y) * (ga1.y * rsqrtf(va1.y + 1e-5f)) + be1.y + r1.y);
    o1.z = sigmoidf((xv1.z - me1.z) * (ga1.z * rsqrtf(va1.z + 1e-5f)) + be1.z + r1.z);
    o1.w = sigmoidf((xv1.w - me1.w) * (ga1.w * rsqrtf(va1.w + 1e-5f)) + be1.w + r1.w);
    ((float4*)out)[base]     = o0;
    ((float4*)out)[base + 1] = o1;
}

// ---------------- fused edge-fill + GEMM1 (interleaved 5:2) ------------------
__global__ void __launch_bounds__(256) edgefill_gemm1_kernel(
    const int* __restrict__ node_idx, const int* __restrict__ edge_idx,
    int* __restrict__ cursors, int* __restrict__ entries, int nnz,
    int fill_blocks, int gemm_blocks,
    const float* __restrict__ X, const float* __restrict__ W,
    const float* __restrict__ bias, __half* __restrict__ out, int M,
    int* __restrict__ scan_flags)
{
    __shared__ __half Xs[128][72];
    __shared__ __half Ws[128][72];

    if (blockIdx.x == 0 && threadIdx.x < NBLK)
        scan_flags[threadIdx.x] = 0;     // reset for next call

    const int grp = blockIdx.x / 7;
    const int rem = blockIdx.x % 7;

    if (rem < 5) {
        int fid = grp * 5 + rem;
        if (fid >= fill_blocks) return;
        int p = 4 * (fid * blockDim.x + threadIdx.x);
        if (p + 4 <= nnz) {
            int4 e = *(const int4*)(edge_idx + p);
            int4 n = *(const int4*)(node_idx + p);
            int s0 = atomicAdd(&cursors[e.x], 1);
            int s1 = atomicAdd(&cursors[e.y], 1);
            int s2 = atomicAdd(&cursors[e.z], 1);
            int s3 = atomicAdd(&cursors[e.w], 1);
            entries[s0] = n.x;
            entries[s1] = n.y;
            entries[s2] = n.z;
            entries[s3] = n.w;
        } else {
            for (; p < nnz; p++) {
                int n = __ldg(node_idx + p);
                int e = __ldg(edge_idx + p);
                int s = atomicAdd(&cursors[e], 1);
                entries[s] = n;
            }
        }
    } else {
        int gid = grp * 2 + (rem - 5);
        if (gid >= gemm_blocks) return;
        gemm_body<false>(Xs, Ws, X, nullptr, W, bias, out, M, gid * 128);
    }
}

// ---------------- fused segsum-edge (half-warp merge) + node-fill (5:4) ------
__global__ void __launch_bounds__(256) segsumE_nodefill_kernel(
    const __half* __restrict__ node_msg,
    const int* __restrict__ entries,
    const int* __restrict__ offsets,
    const float* __restrict__ x1,
    const float* __restrict__ gamma, const float* __restrict__ beta,
    const float* __restrict__ mean, const float* __restrict__ var,
    float* __restrict__ edge_agg, float* __restrict__ x1_out,
    int seg_blocks,
    const int* __restrict__ node_idx, const int* __restrict__ edge_idx,
    int* __restrict__ cursors, int nnz, int fill_blocks)
{
    const int grp = blockIdx.x / 9;
    const int rem = blockIdx.x % 9;

    if (rem < 5) {
        int sid = grp * 5 + rem;
        if (sid >= seg_blocks) return;
        segsum_half_body<true>(node_msg, entries, offsets, x1,
                               gamma, beta, mean, var,
                               edge_agg, x1_out, N_EDGES, sid);
    } else {
        int fid = grp * 4 + (rem - 5);
        if (fid >= fill_blocks) return;
        int p = 4 * (fid * 256 + (int)threadIdx.x);
        int* entries_mut = (int*)entries;
        if (p + 4 <= nnz) {
            int4 e = *(const int4*)(edge_idx + p);
            int4 n = *(const int4*)(node_idx + p);
            int t0 = atomicAdd(&cursors[N_EDGES + n.x], 1);
            int t1 = atomicAdd(&cursors[N_EDGES + n.y], 1);
            int t2 = atomicAdd(&cursors[N_EDGES + n.z], 1);
            int t3 = atomicAdd(&cursors[N_EDGES + n.w], 1);
            entries_mut[t0] = e.x;
            entries_mut[t1] = e.y;
            entries_mut[t2] = e.z;
            entries_mut[t3] = e.w;
        } else {
            for (; p < nnz; p++) {
                int n = __ldg(node_idx + p);
                int e = __ldg(edge_idx + p);
                int q = atomicAdd(&cursors[N_EDGES + n], 1);
                entries_mut[q] = e;
            }
        }
    }
}

// standalone GEMM (used for GEMM2)
template <bool TWO>
__global__ void __launch_bounds__(256) gemm_f16_sig_kernel(
    const float* __restrict__ XA, const float* __restrict__ XB,
    const float* __restrict__ W, const float* __restrict__ bias,
    __half* __restrict__ out, int M)
{
    __shared__ __half Xs[128][72];
    __shared__ __half Ws[128][72];
    gemm_body<TWO>(Xs, Ws, XA, XB, W, bias, out, M, blockIdx.x * 128);
}

// ---------------- launch -----------------------------------------------------
extern "C" void kernel_launch(void* const* d_in, const int* in_sizes, int n_in,
                              void* d_out, int out_size)
{
    const float* x0        = (const float*)d_in[0];
    const float* x1        = (const float*)d_in[1];
    const int*   node_idx  = (const int*)d_in[2];
    const int*   edge_idx  = (const int*)d_in[3];
    const float* W_nh      = (const float*)d_in[4];
    const float* b_nh      = (const float*)d_in[5];
    const float* W_en      = (const float*)d_in[6];
    const float* b_en      = (const float*)d_in[7];
    const float* bn0_gamma = (const float*)d_in[8];
    const float* bn0_beta  = (const float*)d_in[9];
    const float* bn0_mean  = (const float*)d_in[10];
    const float* bn0_var   = (const float*)d_in[11];
    const float* bn1_gamma = (const float*)d_in[12];
    const float* bn1_beta  = (const float*)d_in[13];
    const float* bn1_mean  = (const float*)d_in[14];
    const float* bn1_var   = (const float*)d_in[15];

    float* out = (float*)d_out;
    const int nnz = in_sizes[2];

    __half *node_msg, *he_msg;
    float *edge_agg;
    int *cnt, *offsets, *cursors, *entries, *sagg, *sinc, *sflag;
    cudaGetSymbolAddress((void**)&node_msg, g_node_msg);
    cudaGetSymbolAddress((void**)&edge_agg, g_edge_agg);
    cudaGetSymbolAddress((void**)&he_msg,   g_he_msg);
    cudaGetSymbolAddress((void**)&cnt,      g_cnt);
    cudaGetSymbolAddress((void**)&offsets,  g_offsets);
    cudaGetSymbolAddress((void**)&cursors,  g_cursors);
    cudaGetSymbolAddress((void**)&entries,  g_entries);
    cudaGetSymbolAddress((void**)&sagg,     g_scan_agg);
    cudaGetSymbolAddress((void**)&sinc,     g_scan_inc);
    cudaGetSymbolAddress((void**)&sflag,    g_scan_flag);

    const int pair_blocks  = (nnz + 1023) / 1024;            // 4 pairs/thread
    const int gemm1_blocks = (N_NODES + 127) / 128;

    // --- hist (cnt arrives zeroed: static init first call, scan resets it) ---
    hist_kernel<<<(nnz / 4 + 256) / 256 + 1, 256>>>(node_idx, edge_idx, cnt, nnz);

    // --- one-pass scan (consumes cnt, writes offsets/cursors, re-zeros cnt) ---
    scan_onepass_kernel<<<NBLK, SCAN_BLK>>>(cnt, offsets, cursors,
                                            sagg, sinc, sflag, NSEG, 2 * nnz);

    // --- fused: edge-direction fill + GEMM1, interleaved 5:2 (+flag reset) ---
    {
        const int ngroups = max((pair_blocks + 4) / 5, (gemm1_blocks + 1) / 2);
        edgefill_gemm1_kernel<<<ngroups * 7, 256>>>(
            node_idx, edge_idx, cursors, entries, nnz,
            pair_blocks, gemm1_blocks,
            x0, W_nh, b_nh, node_msg, N_NODES, sflag);
    }

    // --- fused: segsum-edge (half-warp merge, agg + x1_out) + node-fill, 5:4 ---
    {
        const int seg_blocks = (N_EDGES * 32 + 255) / 256;   // 2500
        const int ngroups = max((seg_blocks + 4) / 5, (pair_blocks + 3) / 4);
        segsumE_nodefill_kernel<<<ngroups * 9, 256>>>(
            node_msg, entries, offsets, x1,
            bn1_gamma, bn1_beta, bn1_mean, bn1_var,
            edge_agg, out + (size_t)N_NODES * F, seg_blocks,
            node_idx, edge_idx, cursors, nnz, pair_blocks);
    }

    // --- hyperedge messages ---
    gemm_f16_sig_kernel<true><<<(N_EDGES + 127) / 128, 256>>>(
        x1, edge_agg, W_en, b_en, he_msg, N_EDGES);

    // --- node segments: half-warp-per-segment, fused x0_out epilogue ---
    segsum_node_kernel<<<(N_NODES + 15) / 16, 256>>>(
        he_msg, entries, offsets + N_EDGES, x0,
        bn0_gamma, bn0_beta, bn0_mean, bn0_var,
        out, N_NODES);
}